// round 4
// baseline (speedup 1.0000x reference)
#include <cuda_runtime.h>
#include <cuda_fp16.h>
#include <cstdint>

// ================= problem constants =================
#define BS      65536
#define DDIM    768
#define KC      64                 // K per stage (128B fp16 rows)
#define NITER   12                 // 768 / 64
#define A_BYTES (128 * 128)        // 128 rows x 128B
#define W_BYTES (64 * 128)         // 64 rows x 128B
#define STAGE_BYTES (A_BYTES + 3 * W_BYTES)   // 40960
#define NSTAGE  3
#define SMEM_BYTES (NSTAGE * STAGE_BYTES)     // 122880 (>= 104448 epilogue buf)

// ================= static device scratch (allowed) =================
__device__ __align__(16) __half g_xn2[(size_t)BS * DDIM];   // fp16 LN output
__device__ __align__(16) __half g_w2[3][DDIM * DDIM];       // fp16 Wq,Wk,Wv

// ================= helpers =================
__device__ __forceinline__ uint32_t smem_u32(const void* p) {
    uint32_t a;
    asm("{ .reg .u64 t; cvta.to.shared.u64 t, %1; cvt.u32.u64 %0, t; }" : "=r"(a) : "l"(p));
    return a;
}
__device__ __forceinline__ void cp16(uint32_t dst, const void* src) {
    asm volatile("cp.async.cg.shared.global [%0], [%1], 16;" :: "r"(dst), "l"(src));
}
#define CP_COMMIT() asm volatile("cp.async.commit_group;" ::: "memory")
#define CP_WAIT1()  asm volatile("cp.async.wait_group 1;"  ::: "memory")

__device__ __forceinline__ void ldm4(uint32_t* d, uint32_t addr) {
    asm volatile("ldmatrix.sync.aligned.m8n8.x4.shared.b16 {%0,%1,%2,%3}, [%4];"
                 : "=r"(d[0]), "=r"(d[1]), "=r"(d[2]), "=r"(d[3]) : "r"(addr));
}
__device__ __forceinline__ void hmma(float* c, const uint32_t* a, uint32_t b0, uint32_t b1) {
    asm volatile(
        "mma.sync.aligned.m16n8k16.row.col.f32.f16.f16.f32 "
        "{%0,%1,%2,%3},{%4,%5,%6,%7},{%8,%9},{%0,%1,%2,%3};"
        : "+f"(c[0]), "+f"(c[1]), "+f"(c[2]), "+f"(c[3])
        : "r"(a[0]), "r"(a[1]), "r"(a[2]), "r"(a[3]), "r"(b0), "r"(b1));
}

// ================= kernel 0: W -> fp16 =================
__global__ void __launch_bounds__(256) prep_w_kernel(const float* __restrict__ wq,
                                                     const float* __restrict__ wk,
                                                     const float* __restrict__ wv) {
    int i = blockIdx.x * blockDim.x + threadIdx.x;  // float4 idx: 768*768/4
    const float* srcs[3] = {wq, wk, wv};
#pragma unroll
    for (int m = 0; m < 3; m++) {
        float4 v = ((const float4*)srcs[m])[i];
        union { __half2 h[2]; uint2 u; } cvt;
        cvt.h[0] = __floats2half2_rn(v.x, v.y);
        cvt.h[1] = __floats2half2_rn(v.z, v.w);
        ((uint2*)g_w2[m])[i] = cvt.u;
    }
}

// ================= kernel 1: layernorm -> fp16 xn =================
__global__ void __launch_bounds__(256) ln_kernel(const float* __restrict__ x,
                                                 const float* __restrict__ gamma,
                                                 const float* __restrict__ beta) {
    const int row  = blockIdx.x * 8 + (threadIdx.x >> 5);
    const int lane = threadIdx.x & 31;
    const float4* xr = (const float4*)(x + (size_t)row * DDIM);
    float4 v[6];
    float s = 0.f;
#pragma unroll
    for (int i = 0; i < 6; i++) {
        v[i] = xr[lane + 32 * i];
        s += v[i].x + v[i].y + v[i].z + v[i].w;
    }
#pragma unroll
    for (int o = 16; o; o >>= 1) s += __shfl_xor_sync(0xffffffffu, s, o);
    const float mu = s * (1.0f / 768.0f);
    float ss = 0.f;
#pragma unroll
    for (int i = 0; i < 6; i++) {
        float a = v[i].x - mu, b = v[i].y - mu, c = v[i].z - mu, d = v[i].w - mu;
        ss += a * a + b * b + c * c + d * d;
    }
#pragma unroll
    for (int o = 16; o; o >>= 1) ss += __shfl_xor_sync(0xffffffffu, ss, o);
    const float inv = rsqrtf(ss * (1.0f / 768.0f) + 1e-6f);
    const float4* g4 = (const float4*)gamma;
    const float4* b4 = (const float4*)beta;
    uint2* dst = (uint2*)(g_xn2 + (size_t)row * DDIM);
#pragma unroll
    for (int i = 0; i < 6; i++) {
        float4 g = g4[lane + 32 * i];
        float4 bb = b4[lane + 32 * i];
        union { __half2 h[2]; uint2 u; } cvt;
        cvt.h[0] = __floats2half2_rn((v[i].x - mu) * inv * g.x + bb.x,
                                     (v[i].y - mu) * inv * g.y + bb.y);
        cvt.h[1] = __floats2half2_rn((v[i].z - mu) * inv * g.z + bb.z,
                                     (v[i].w - mu) * inv * g.w + bb.w);
        dst[lane + 32 * i] = cvt.u;
    }
}

// ================= stage loader: 2560 x 16B chunks, SW128 swizzle ==========
__device__ __forceinline__ void load_stage(uint32_t st, int k0, int row0, int col0, int tid) {
#pragma unroll
    for (int i = 0; i < 10; i++) {
        int s = tid + 256 * i;          // 0..2559
        if (s < 1024) {                 // A tile: 128 rows x 8 chunks
            int r = s >> 3, c = s & 7;
            const __half* src = g_xn2 + (size_t)(row0 + r) * DDIM + k0 + 8 * c;
            cp16(st + (r << 7) + (((uint32_t)c ^ (r & 7)) << 4), src);
        } else {                        // W tiles: 3 x 64 rows x 8 chunks
            int s2 = s - 1024;
            int m = s2 >> 9, idx = s2 & 511;
            int r = idx >> 3, c = idx & 7;
            const __half* src = g_w2[m] + (size_t)(col0 + r) * DDIM + k0 + 8 * c;
            cp16(st + A_BYTES + (m << 13) + (r << 7) + (((uint32_t)c ^ (r & 7)) << 4), src);
        }
    }
}

// ================= kernel 2: fused QKV GEMM + 2x2 attention + residual =====
__global__ void __launch_bounds__(256, 1) attn_kernel(const float* __restrict__ x,
                                                      float* __restrict__ out) {
    extern __shared__ __align__(1024) char smem[];
    const uint32_t sb = smem_u32(smem);
    const int tid  = threadIdx.x;
    const int wid  = tid >> 5;
    const int lane = tid & 31;
    const int wm   = wid & 3;        // M block (32 rows)
    const int wn   = wid >> 2;       // N block (32 cols)
    const int head = blockIdx.x;     // 0..11
    const int row0 = blockIdx.y * 128;
    const int col0 = head * 64;

    // ---- per-lane ldmatrix row precompute ----
    // A fragment rows (16x16 tile, x4): row = base + (L&7) + 8*((L>>3)&1), chunk += (L>>4)
    int rA0 = 32 * wm + (lane & 7) + 8 * ((lane >> 3) & 1);
    uint32_t offA[2] = { (uint32_t)(rA0 << 7), (uint32_t)((rA0 + 16) << 7) };
    uint32_t swA[2]  = { (uint32_t)(rA0 & 7),  (uint32_t)((rA0 + 16) & 7) };
    const uint32_t chA = lane >> 4;
    // B fragment rows (n-major): row = base + (L&7) + 8*(L>>4), chunk += (L>>3)&1
    int rB0 = 32 * wn + (lane & 7) + 8 * (lane >> 4);
    uint32_t offB[2] = { (uint32_t)(rB0 << 7), (uint32_t)((rB0 + 16) << 7) };
    uint32_t swB[2]  = { (uint32_t)(rB0 & 7),  (uint32_t)((rB0 + 16) & 7) };
    const uint32_t chB = (lane >> 3) & 1;

    float acc[3][2][4][4];
#pragma unroll
    for (int m = 0; m < 3; m++)
#pragma unroll
        for (int a = 0; a < 2; a++)
#pragma unroll
            for (int b = 0; b < 4; b++)
#pragma unroll
                for (int c = 0; c < 4; c++) acc[m][a][b][c] = 0.f;

    // ---- prologue: prefetch stages 0,1 ----
    load_stage(sb + 0 * STAGE_BYTES, 0,  row0, col0, tid); CP_COMMIT();
    load_stage(sb + 1 * STAGE_BYTES, KC, row0, col0, tid); CP_COMMIT();

    // ---- main loop ----
    for (int c = 0; c < NITER; c++) {
        CP_WAIT1();
        __syncthreads();
        if (c + 2 < NITER)
            load_stage(sb + (uint32_t)((c + 2) % NSTAGE) * STAGE_BYTES,
                       (c + 2) * KC, row0, col0, tid);
        CP_COMMIT();

        const uint32_t st = sb + (uint32_t)(c % NSTAGE) * STAGE_BYTES;
#pragma unroll
        for (int ks = 0; ks < 4; ks++) {
            uint32_t a[2][4];
#pragma unroll
            for (int mt = 0; mt < 2; mt++)
                ldm4(a[mt], st + offA[mt] + ((((uint32_t)(2 * ks) + chA) ^ swA[mt]) << 4));
#pragma unroll
            for (int m = 0; m < 3; m++) {
                const uint32_t stw = st + A_BYTES + (m << 13);
                uint32_t b[2][4];
#pragma unroll
                for (int p = 0; p < 2; p++)
                    ldm4(b[p], stw + offB[p] + ((((uint32_t)(2 * ks) + chB) ^ swB[p]) << 4));
#pragma unroll
                for (int mt = 0; mt < 2; mt++) {
                    hmma(acc[m][mt][0], a[mt], b[0][0], b[0][1]);
                    hmma(acc[m][mt][1], a[mt], b[0][2], b[0][3]);
                    hmma(acc[m][mt][2], a[mt], b[1][0], b[1][1]);
                    hmma(acc[m][mt][3], a[mt], b[1][2], b[1][3]);
                }
            }
        }
    }

    // ---- epilogue: acc -> smem buffers [3][128][68] fp32 ----
    __syncthreads();   // all ldmatrix reads done; smem reusable
    float* sbuf = (float*)smem;
    const int g  = lane >> 2;        // row-in-tile
    const int tg = lane & 3;         // col pair
#pragma unroll
    for (int m = 0; m < 3; m++) {
        float* bm = sbuf + m * (128 * 68);
#pragma unroll
        for (int mt = 0; mt < 2; mt++) {
            const int r0 = 32 * wm + 16 * mt + g;
#pragma unroll
            for (int nt = 0; nt < 4; nt++) {
                const int cb = 32 * wn + 8 * nt + 2 * tg;
                *(float2*)(bm + (size_t)r0 * 68 + cb)       = make_float2(acc[m][mt][nt][0], acc[m][mt][nt][1]);
                *(float2*)(bm + (size_t)(r0 + 8) * 68 + cb) = make_float2(acc[m][mt][nt][2], acc[m][mt][nt][3]);
            }
        }
    }
    __syncthreads();

    // ---- per-(row,p) 2x2 attention + residual ----
    {
        const int row = tid >> 1;            // 0..127
        const int p   = tid & 1;
        const float* qb = sbuf + (size_t)row * 68 + 32 * p;
        const float* kb = sbuf + 128 * 68 + (size_t)row * 68;
        const float* vb = sbuf + 2 * 128 * 68 + (size_t)row * 68;
        float s0 = 0.f, s1 = 0.f;
#pragma unroll
        for (int d = 0; d < 32; d++) {
            float q = qb[d];
            s0 += q * kb[d];
            s1 += q * kb[32 + d];
        }
        const float sc = 0.17677669529663687f;  // 1/sqrt(32)
        s0 *= sc; s1 *= sc;
        float mx = fmaxf(s0, s1);
        float e0 = __expf(s0 - mx), e1 = __expf(s1 - mx);
        float rs = 1.0f / (e0 + e1);
        float a0 = e0 * rs, a1 = e1 * rs;

        const size_t base = (size_t)(row0 + row) * DDIM + col0 + 32 * p;
        const float4* xi = (const float4*)(x + base);
        float4* op = (float4*)(out + base);
#pragma unroll
        for (int i = 0; i < 8; i++) {
            float4 xv = xi[i];
            float4 o;
            o.x = a0 * vb[4 * i + 0] + a1 * vb[32 + 4 * i + 0] + xv.x;
            o.y = a0 * vb[4 * i + 1] + a1 * vb[32 + 4 * i + 1] + xv.y;
            o.z = a0 * vb[4 * i + 2] + a1 * vb[32 + 4 * i + 2] + xv.z;
            o.w = a0 * vb[4 * i + 3] + a1 * vb[32 + 4 * i + 3] + xv.w;
            op[i] = o;
        }
    }
}

// ================= launch =================
extern "C" void kernel_launch(void* const* d_in, const int* in_sizes, int n_in,
                              void* d_out, int out_size) {
    const float* x     = (const float*)d_in[0];
    const float* Wq    = (const float*)d_in[1];
    const float* Wk    = (const float*)d_in[2];
    const float* Wv    = (const float*)d_in[3];
    const float* gamma = (const float*)d_in[4];
    const float* beta  = (const float*)d_in[5];
    float* out = (float*)d_out;

    cudaFuncSetAttribute(attn_kernel, cudaFuncAttributeMaxDynamicSharedMemorySize, SMEM_BYTES);

    prep_w_kernel<<<(DDIM * DDIM / 4) / 256, 256>>>(Wq, Wk, Wv);
    ln_kernel<<<BS / 8, 256>>>(x, gamma, beta);
    attn_kernel<<<dim3(12, BS / 128), 256, SMEM_BYTES>>>(x, out);
}

// round 5
// speedup vs baseline: 1.0200x; 1.0200x over previous
#include <cuda_runtime.h>
#include <cuda_fp16.h>
#include <cstdint>

// ================= problem constants =================
#define BS      65536
#define DDIM    768
#define NHEAD   12
#define KC      64                  // K per chunk (128B fp16 rows)
#define CPT     12                  // chunks per tile (768/64)
#define NTILES  6144                // (BS/128) * NHEAD
#define GRID    148
#define A_BYTES (128 * 128)         // 128 rows x 128B
#define W_BYTES (64 * 128)          // 64 rows x 128B
#define STAGE_BYTES (A_BYTES + 3 * W_BYTES)   // 40960
#define NSTAGE  4
#define SMEM_BYTES (NSTAGE * STAGE_BYTES)     // 163840

// ================= static device scratch (allowed) =================
__device__ __align__(16) __half g_xn2[(size_t)BS * DDIM];   // fp16 LN output
__device__ __align__(16) __half g_w2[3][DDIM * DDIM];       // fp16 Wq,Wk,Wv

// ================= helpers =================
__device__ __forceinline__ uint32_t smem_u32(const void* p) {
    uint32_t a;
    asm("{ .reg .u64 t; cvta.to.shared.u64 t, %1; cvt.u32.u64 %0, t; }" : "=r"(a) : "l"(p));
    return a;
}
__device__ __forceinline__ void cp16(uint32_t dst, const void* src) {
    asm volatile("cp.async.cg.shared.global [%0], [%1], 16;" :: "r"(dst), "l"(src));
}
#define CP_COMMIT() asm volatile("cp.async.commit_group;" ::: "memory")
#define CP_WAITG2() asm volatile("cp.async.wait_group 2;"  ::: "memory")

__device__ __forceinline__ void ldm4(uint32_t* d, uint32_t addr) {
    asm volatile("ldmatrix.sync.aligned.m8n8.x4.shared.b16 {%0,%1,%2,%3}, [%4];"
                 : "=r"(d[0]), "=r"(d[1]), "=r"(d[2]), "=r"(d[3]) : "r"(addr));
}
__device__ __forceinline__ void hmma(float* c, const uint32_t* a, uint32_t b0, uint32_t b1) {
    asm volatile(
        "mma.sync.aligned.m16n8k16.row.col.f32.f16.f16.f32 "
        "{%0,%1,%2,%3},{%4,%5,%6,%7},{%8,%9},{%0,%1,%2,%3};"
        : "+f"(c[0]), "+f"(c[1]), "+f"(c[2]), "+f"(c[3])
        : "r"(a[0]), "r"(a[1]), "r"(a[2]), "r"(a[3]), "r"(b0), "r"(b1));
}

// ================= kernel 0: fused W->fp16 conversion + layernorm ==========
__global__ void __launch_bounds__(256) prep_kernel(const float* __restrict__ x,
                                                   const float* __restrict__ wq,
                                                   const float* __restrict__ wk,
                                                   const float* __restrict__ wv,
                                                   const float* __restrict__ gamma,
                                                   const float* __restrict__ beta) {
    if (blockIdx.x < 576) {
        // ---- weight conversion: 576*256 = 147456 float4 per matrix ----
        int i = blockIdx.x * 256 + threadIdx.x;
        const float* srcs[3] = {wq, wk, wv};
#pragma unroll
        for (int m = 0; m < 3; m++) {
            float4 v = ((const float4*)srcs[m])[i];
            union { __half2 h[2]; uint2 u; } cvt;
            cvt.h[0] = __floats2half2_rn(v.x, v.y);
            cvt.h[1] = __floats2half2_rn(v.z, v.w);
            ((uint2*)g_w2[m])[i] = cvt.u;
        }
        return;
    }
    // ---- layernorm: 8 rows per block ----
    const int row  = (blockIdx.x - 576) * 8 + (threadIdx.x >> 5);
    const int lane = threadIdx.x & 31;
    const float4* xr = (const float4*)(x + (size_t)row * DDIM);
    float4 v[6];
    float s = 0.f;
#pragma unroll
    for (int i = 0; i < 6; i++) {
        v[i] = xr[lane + 32 * i];
        s += v[i].x + v[i].y + v[i].z + v[i].w;
    }
#pragma unroll
    for (int o = 16; o; o >>= 1) s += __shfl_xor_sync(0xffffffffu, s, o);
    const float mu = s * (1.0f / 768.0f);
    float ss = 0.f;
#pragma unroll
    for (int i = 0; i < 6; i++) {
        float a = v[i].x - mu, b = v[i].y - mu, c = v[i].z - mu, d = v[i].w - mu;
        ss += a * a + b * b + c * c + d * d;
    }
#pragma unroll
    for (int o = 16; o; o >>= 1) ss += __shfl_xor_sync(0xffffffffu, ss, o);
    const float inv = rsqrtf(ss * (1.0f / 768.0f) + 1e-6f);
    const float4* g4 = (const float4*)gamma;
    const float4* b4 = (const float4*)beta;
    uint2* dst = (uint2*)(g_xn2 + (size_t)row * DDIM);
#pragma unroll
    for (int i = 0; i < 6; i++) {
        float4 g = g4[lane + 32 * i];
        float4 bb = b4[lane + 32 * i];
        union { __half2 h[2]; uint2 u; } cvt;
        cvt.h[0] = __floats2half2_rn((v[i].x - mu) * inv * g.x + bb.x,
                                     (v[i].y - mu) * inv * g.y + bb.y);
        cvt.h[1] = __floats2half2_rn((v[i].z - mu) * inv * g.z + bb.z,
                                     (v[i].w - mu) * inv * g.w + bb.w);
        dst[lane + 32 * i] = cvt.u;
    }
}

// ================= stage loader: 2560 x 16B chunks, SW128 swizzle ==========
__device__ __forceinline__ void load_stage(uint32_t st, int k0, int row0, int col0, int tid) {
#pragma unroll
    for (int i = 0; i < 10; i++) {
        int s = tid + 256 * i;          // 0..2559 (branch uniform per unrolled i)
        if (s < 1024) {                 // A tile: 128 rows x 8 chunks
            int r = s >> 3, c = s & 7;
            const __half* src = g_xn2 + (size_t)(row0 + r) * DDIM + k0 + 8 * c;
            cp16(st + (r << 7) + (((uint32_t)c ^ (r & 7)) << 4), src);
        } else {                        // W tiles: 3 x 64 rows x 8 chunks
            int s2 = s - 1024;
            int m = s2 >> 9, idx = s2 & 511;
            int r = idx >> 3, c = idx & 7;
            const __half* src = g_w2[m] + (size_t)(col0 + r) * DDIM + k0 + 8 * c;
            cp16(st + A_BYTES + (m << 13) + (r << 7) + (((uint32_t)c ^ (r & 7)) << 4), src);
        }
    }
}

// chunk index -> (k0, row0, col0)
__device__ __forceinline__ void coords(int bid, int l, int& k0, int& row0, int& col0) {
    int tl = l / CPT;
    int c  = l - tl * CPT;
    int t  = bid + GRID * tl;
    int rb = t / NHEAD;
    k0   = c * KC;
    row0 = rb * 128;
    col0 = (t - rb * NHEAD) * 64;
}

// ================= kernel 1: persistent fused QKV GEMM + attention =========
__global__ void __launch_bounds__(256, 1) attn_kernel(const float* __restrict__ x,
                                                      float* __restrict__ out) {
    extern __shared__ __align__(1024) char smem[];
    const uint32_t sb = smem_u32(smem);
    const int tid  = threadIdx.x;
    const int wid  = tid >> 5;
    const int lane = tid & 31;
    const int bid  = blockIdx.x;

    const int ntiles = 41 + (bid < (NTILES - 41 * GRID) ? 1 : 0);  // 76 CTAs get 42
    const int L = ntiles * CPT;

    // ldmatrix lane constants (warp owns 16 rows x 64 cols)
    const uint32_t sw   = lane & 7;
    const uint32_t offA = (uint32_t)((16 * wid + (lane & 7) + 8 * ((lane >> 3) & 1)) << 7);
    const uint32_t chA  = lane >> 4;
    const uint32_t rB   = (lane & 7) + 8 * (lane >> 4);
    const uint32_t chB  = (lane >> 3) & 1;

    float acc[3][8][4];
#pragma unroll
    for (int m = 0; m < 3; m++)
#pragma unroll
        for (int n = 0; n < 8; n++)
#pragma unroll
            for (int e = 0; e < 4; e++) acc[m][n][e] = 0.f;

    // ---- prologue: prefetch chunks 0..2 ----
#pragma unroll
    for (int l = 0; l < 3; l++) {
        int k0, r0, c0;
        coords(bid, l, k0, r0, c0);
        load_stage(sb + (uint32_t)l * STAGE_BYTES, k0, r0, c0, tid);
        CP_COMMIT();
    }

    // ---- persistent main loop over all chunks of all tiles ----
    for (int l = 0; l < L; l++) {
        CP_WAITG2();
        __syncthreads();

        const uint32_t st = sb + (uint32_t)(l & 3) * STAGE_BYTES;
#pragma unroll
        for (int ks = 0; ks < 4; ks++) {
            uint32_t a[4];
            ldm4(a, st + offA + ((((uint32_t)(2 * ks) + chA) ^ sw) << 4));
#pragma unroll
            for (int m = 0; m < 3; m++) {
                const uint32_t stw = st + A_BYTES + (m << 13);
                uint32_t b[4][4];
#pragma unroll
                for (int j = 0; j < 4; j++)
                    ldm4(b[j], stw + ((16u * j + rB) << 7)
                                   + ((((uint32_t)(2 * ks) + chB) ^ sw) << 4));
#pragma unroll
                for (int j = 0; j < 4; j++) {
                    hmma(acc[m][2 * j],     a, b[j][0], b[j][1]);
                    hmma(acc[m][2 * j + 1], a, b[j][2], b[j][3]);
                }
            }
        }

        // prefetch chunk l+3 (may belong to the next tile)
        int lp = l + 3;
        if (lp < L) {
            int k0, r0, c0;
            coords(bid, lp, k0, r0, c0);
            load_stage(sb + (uint32_t)(lp & 3) * STAGE_BYTES, k0, r0, c0, tid);
        }
        CP_COMMIT();

        // ---- tile finished: register-only 2x2 attention epilogue ----
        if ((l % CPT) == CPT - 1) {
            int t    = bid + GRID * (l / CPT);
            int rb   = t / NHEAD;
            int row0 = rb * 128;
            int col0 = (t - rb * NHEAD) * 64;
            const int g  = lane >> 2;
            const int tg = lane & 3;
            const float sc = 0.17677669529663687f;  // 1/sqrt(32)

#pragma unroll
            for (int h = 0; h < 2; h++) {            // two 8-row halves
                float s00 = 0.f, s01 = 0.f, s10 = 0.f, s11 = 0.f;
#pragma unroll
                for (int nt = 0; nt < 4; nt++)
#pragma unroll
                    for (int e = 0; e < 2; e++) {
                        int ei = 2 * h + e;
                        float q0 = acc[0][nt][ei],     q1 = acc[0][nt + 4][ei];
                        float k0v = acc[1][nt][ei],    k1v = acc[1][nt + 4][ei];
                        s00 += q0 * k0v; s01 += q0 * k1v;
                        s10 += q1 * k0v; s11 += q1 * k1v;
                    }
                // quad reduce (lanes differing in tg only)
                s00 += __shfl_xor_sync(0xffffffffu, s00, 1);
                s00 += __shfl_xor_sync(0xffffffffu, s00, 2);
                s01 += __shfl_xor_sync(0xffffffffu, s01, 1);
                s01 += __shfl_xor_sync(0xffffffffu, s01, 2);
                s10 += __shfl_xor_sync(0xffffffffu, s10, 1);
                s10 += __shfl_xor_sync(0xffffffffu, s10, 2);
                s11 += __shfl_xor_sync(0xffffffffu, s11, 1);
                s11 += __shfl_xor_sync(0xffffffffu, s11, 2);
                s00 *= sc; s01 *= sc; s10 *= sc; s11 *= sc;

                float m0 = fmaxf(s00, s01), m1 = fmaxf(s10, s11);
                float e00 = __expf(s00 - m0), e01 = __expf(s01 - m0);
                float e10 = __expf(s10 - m1), e11 = __expf(s11 - m1);
                float r0 = 1.0f / (e00 + e01), r1 = 1.0f / (e10 + e11);
                float a00 = e00 * r0, a01 = e01 * r0;
                float a10 = e10 * r1, a11 = e11 * r1;

                const int row = row0 + 16 * wid + g + 8 * h;
                const float* xr = x + (size_t)row * DDIM + col0;
                float* orow = out + (size_t)row * DDIM + col0;
#pragma unroll
                for (int nt = 0; nt < 4; nt++) {
                    int c0 = 8 * nt + 2 * tg;
                    float v0a = acc[2][nt][2 * h],     v0b = acc[2][nt][2 * h + 1];
                    float v1a = acc[2][nt + 4][2 * h], v1b = acc[2][nt + 4][2 * h + 1];
                    float2 xv0 = *(const float2*)(xr + c0);
                    float2 xv1 = *(const float2*)(xr + 32 + c0);
                    float2 o0, o1;
                    o0.x = a00 * v0a + a01 * v1a + xv0.x;
                    o0.y = a00 * v0b + a01 * v1b + xv0.y;
                    o1.x = a10 * v0a + a11 * v1a + xv1.x;
                    o1.y = a10 * v0b + a11 * v1b + xv1.y;
                    *(float2*)(orow + c0)      = o0;
                    *(float2*)(orow + 32 + c0) = o1;
                }
            }
            // reset accumulators for the next tile
#pragma unroll
            for (int m = 0; m < 3; m++)
#pragma unroll
                for (int n = 0; n < 8; n++)
#pragma unroll
                    for (int e = 0; e < 4; e++) acc[m][n][e] = 0.f;
        }
    }
}

// ================= launch =================
extern "C" void kernel_launch(void* const* d_in, const int* in_sizes, int n_in,
                              void* d_out, int out_size) {
    const float* x     = (const float*)d_in[0];
    const float* Wq    = (const float*)d_in[1];
    const float* Wk    = (const float*)d_in[2];
    const float* Wv    = (const float*)d_in[3];
    const float* gamma = (const float*)d_in[4];
    const float* beta  = (const float*)d_in[5];
    float* out = (float*)d_out;

    cudaFuncSetAttribute(attn_kernel, cudaFuncAttributeMaxDynamicSharedMemorySize, SMEM_BYTES);

    prep_kernel<<<576 + BS / 8, 256>>>(x, Wq, Wk, Wv, gamma, beta);
    attn_kernel<<<GRID, 256, SMEM_BYTES>>>(x, out);
}